// round 1
// baseline (speedup 1.0000x reference)
#include <cuda_runtime.h>
#include <math.h>

// Problem constants
#define NB   256   // batch
#define NL   256   // sequence length (== LB)
#define NC   32    // channels
#define NS   32    // states
#define NROWS (NB*NL)
#define C_LOG2PI 58.812066125099048f   // 32 * log(2*pi)

#define FULLMASK 0xffffffffu
typedef unsigned long long ull;

// ---------------- packed f32x2 helpers ----------------
__device__ __forceinline__ ull pack2(float a, float b) {
    ull r; asm("mov.b64 %0, {%1, %2};" : "=l"(r) : "f"(a), "f"(b)); return r;
}
__device__ __forceinline__ float2 unpack2(ull v) {
    float2 r; asm("mov.b64 {%0, %1}, %2;" : "=f"(r.x), "=f"(r.y) : "l"(v)); return r;
}
__device__ __forceinline__ ull fma2(ull a, ull b, ull c) {
    ull d; asm("fma.rn.f32x2 %0, %1, %2, %3;" : "=l"(d) : "l"(a), "l"(b), "l"(c)); return d;
}
__device__ __forceinline__ ull add2(ull a, ull b) {
    ull d; asm("add.rn.f32x2 %0, %1, %2;" : "=l"(d) : "l"(a), "l"(b)); return d;
}

// ---------------- device scratch (allocation-free) ----------------
__device__ ull   g_Linv2[NS * 528];      // triangular-packed Linv, each element duplicated (float2)
__device__ ull   g_negmu2[NS * NC];      // -mu duplicated
__device__ float g_ld[NS];               // logdet per state
__device__ float g_log_trans[NS * NS];   // log(softmax(T)+1e-8)
__device__ float g_log_init[NS];         // log softmax of initial distribution
__device__ int   g_rowargmax[NS];        // argmax of each transition row
__device__ int   g_state2[NB];           // final state per batch (after one trans step)
__device__ float g_emlp[NROWS * NS];     // emission log probs, [b*L+t][s]

// =====================================================================
// Kernel 0: per-state prep (blocks 0..31) + transition/init prep (block 32)
// One warp per block.
// =====================================================================
__global__ void prep_kernel(const float* __restrict__ cc,      // covar_chol (S,C,C)
                            const float* __restrict__ means,   // (S,C)
                            const float* __restrict__ tm,      // transition (S,S)
                            const float* __restrict__ idist) { // (S,)
    const int lane = threadIdx.x;
    const int s = blockIdx.x;

    if (s < NS) {
        __shared__ float T[32][33];
        __shared__ float A[32][33];
        __shared__ float LI[32][33];

        // Load T = tril(cc[s]) with exp on diagonal
        for (int i = 0; i < 32; i++) {
            float v = cc[s * 1024 + i * 32 + lane];
            if (lane > i) v = 0.0f;
            else if (lane == i) v = expf(v);
            T[i][lane] = v;
        }
        __syncwarp();

        // covar = T T^t + 1e-6 I   (A[i][lane])
        for (int i = 0; i < 32; i++) {
            float acc = (lane == i) ? 1e-6f : 0.0f;
            #pragma unroll
            for (int k = 0; k < 32; k++) acc += T[i][k] * T[lane][k];
            A[i][lane] = acc;
        }
        __syncwarp();

        // In-place Cholesky (lower) of A
        for (int k = 0; k < 32; k++) {
            float d = sqrtf(A[k][k]);       // all lanes read before any write
            __syncwarp();
            if (lane == k) A[k][k] = d;
            if (lane > k)  A[lane][k] = A[lane][k] / d;
            __syncwarp();
            if (lane > k) {
                float lik = A[lane][k];
                for (int j = k + 1; j <= lane; j++) A[lane][j] -= lik * A[j][k];
            }
            __syncwarp();
        }

        // Triangular inverse: lane owns column `lane` of LI
        for (int i = 0; i < 32; i++) {
            float val = 0.0f;
            if (i >= lane) {
                float ss = (i == lane) ? 1.0f : 0.0f;
                for (int k = lane; k < i; k++) ss -= A[i][k] * LI[k][lane];
                val = ss / A[i][i];
            }
            LI[i][lane] = val;
        }
        __syncwarp();

        // logdet = 2 * sum(log(diag))
        float dl = logf(A[lane][lane]);
        #pragma unroll
        for (int o = 16; o; o >>= 1) dl += __shfl_xor_sync(FULLMASK, dl, o);
        if (lane == 0) g_ld[s] = 2.0f * dl;

        // -mu duplicated
        float nm = -means[s * 32 + lane];
        g_negmu2[s * 32 + lane] = pack2(nm, nm);

        // triangular-packed duplicated Linv
        for (int idx = lane; idx < 528; idx += 32) {
            int i = (int)((sqrtf(8.0f * (float)idx + 1.0f) - 1.0f) * 0.5f);
            while ((i + 1) * (i + 2) / 2 <= idx) i++;
            while (i * (i + 1) / 2 > idx) i--;
            int j = idx - i * (i + 1) / 2;
            float v = LI[i][j];
            g_Linv2[s * 528 + idx] = pack2(v, v);
        }
    } else {
        // ---- block 32: log-softmax of init, log(softmax+1e-8) of transition, row argmax
        float v = idist[lane];
        float mx = v;
        #pragma unroll
        for (int o = 16; o; o >>= 1) mx = fmaxf(mx, __shfl_xor_sync(FULLMASK, mx, o));
        float e = expf(v - mx);
        float sm = e;
        #pragma unroll
        for (int o = 16; o; o >>= 1) sm += __shfl_xor_sync(FULLMASK, sm, o);
        g_log_init[lane] = (v - mx) - logf(sm);

        for (int i = 0; i < 32; i++) {
            float tv = tm[i * 32 + lane];
            float m2 = tv;
            #pragma unroll
            for (int o = 16; o; o >>= 1) m2 = fmaxf(m2, __shfl_xor_sync(FULLMASK, m2, o));
            float ee = expf(tv - m2);
            float ssum = ee;
            #pragma unroll
            for (int o = 16; o; o >>= 1) ssum += __shfl_xor_sync(FULLMASK, ssum, o);
            g_log_trans[i * 32 + lane] = logf(ee / ssum + 1e-8f);

            // first-occurrence argmax of the row (softmax is monotone)
            float bv = tv; int bi = lane;
            #pragma unroll
            for (int o = 16; o; o >>= 1) {
                float ov = __shfl_xor_sync(FULLMASK, bv, o);
                int   oi = __shfl_xor_sync(FULLMASK, bi, o);
                if (ov > bv || (ov == bv && oi < bi)) { bv = ov; bi = oi; }
            }
            if (lane == 0) g_rowargmax[i] = bi;
        }
    }
}

// =====================================================================
// Kernel 1: emission log probs.
// 2 rows per thread via packed f32x2; Linv duplicated in smem (broadcast LDS.64).
// Block = 256 threads -> 512 rows. Grid = 128.
// =====================================================================
__global__ void __launch_bounds__(256) emlp_kernel(const float* __restrict__ em) {
    extern __shared__ ull sh[];
    ull*   sL  = sh;                 // 16896 entries (Linv duplicated, tri-packed per state)
    ull*   sM  = sh + 16896;         // 1024 entries (-mu duplicated)
    float* sLd = (float*)(sh + 16896 + 1024);

    for (int idx = threadIdx.x; idx < 16896; idx += 256) sL[idx] = g_Linv2[idx];
    for (int idx = threadIdx.x; idx < 1024;  idx += 256) sM[idx] = g_negmu2[idx];
    if (threadIdx.x < 32) sLd[threadIdx.x] = g_ld[threadIdx.x];
    __syncthreads();

    const int row0 = (blockIdx.x * 256 + threadIdx.x) * 2;
    const float4* p = (const float4*)(em + (size_t)row0 * 32);

    float x0[32], x1[32];
    #pragma unroll
    for (int q = 0; q < 8; q++) {
        float4 a = p[q];
        float4 b = p[8 + q];
        x0[4*q+0] = a.x; x0[4*q+1] = a.y; x0[4*q+2] = a.z; x0[4*q+3] = a.w;
        x1[4*q+0] = b.x; x1[4*q+1] = b.y; x1[4*q+2] = b.z; x1[4*q+3] = b.w;
    }
    ull xp[32];
    #pragma unroll
    for (int j = 0; j < 32; j++) xp[j] = pack2(x0[j], x1[j]);

    float* out0 = g_emlp + (size_t)row0 * NS;

    for (int s = 0; s < NS; s++) {
        const ull* Ls = sL + s * 528;
        const ull* nm = sM + s * 32;

        ull xd[32];
        #pragma unroll
        for (int j = 0; j < 32; j++) xd[j] = add2(xp[j], nm[j]);  // x - mu (both rows)

        ull macc = 0ull;  // (0.f, 0.f)
        #pragma unroll
        for (int i = 0; i < 32; i++) {
            ull acc = 0ull;
            const int tri = i * (i + 1) / 2;
            #pragma unroll
            for (int j = 0; j <= i; j++)
                acc = fma2(Ls[tri + j], xd[j], acc);    // solved_i (both rows)
            macc = fma2(acc, acc, macc);                 // mahal += solved^2
        }
        float2 m = unpack2(macc);
        const float ldv = sLd[s];
        out0[s]      = -0.5f * ((m.x + ldv) + C_LOG2PI);
        out0[NS + s] = -0.5f * ((m.y + ldv) + C_LOG2PI);
    }
}

// =====================================================================
// Kernel 2: Viterbi max-plus recursion. One warp per batch; lane = state.
// =====================================================================
__global__ void viterbi_kernel() {
    const int b = blockIdx.x;
    const int lane = threadIdx.x;

    float ltcol[32];
    #pragma unroll
    for (int i = 0; i < 32; i++) ltcol[i] = g_log_trans[i * 32 + lane];

    const float* eb = g_emlp + (size_t)b * NL * NS;
    float delta = g_log_init[lane] + eb[lane];

    #pragma unroll 4
    for (int t = 1; t < NL; t++) {
        const float emv = eb[t * NS + lane];
        float v[32];
        #pragma unroll
        for (int i = 0; i < 32; i++)
            v[i] = __shfl_sync(FULLMASK, delta, i) + ltcol[i];
        #pragma unroll
        for (int st = 16; st >= 1; st >>= 1) {
            #pragma unroll
            for (int i = 0; i < 16; i++)
                if (i < st) v[i] = fmaxf(v[i], v[i + st]);
        }
        delta = v[0] + emv;
    }

    // first-occurrence argmax over lanes
    float bv = delta; int bi = lane;
    #pragma unroll
    for (int o = 16; o; o >>= 1) {
        float ov = __shfl_xor_sync(FULLMASK, bv, o);
        int   oi = __shfl_xor_sync(FULLMASK, bi, o);
        if (ov > bv || (ov == bv && oi < bi)) { bv = ov; bi = oi; }
    }
    if (lane == 0) g_state2[b] = g_rowargmax[bi];
}

// =====================================================================
// Kernel 3: AR prediction. Block per batch; 256 threads = (8 l-groups x 32 channels).
// =====================================================================
__global__ void predict_kernel(const float* __restrict__ em,
                               const float* __restrict__ W,
                               const float* __restrict__ means,
                               float* __restrict__ out) {
    const int b = blockIdx.x;
    const int c = threadIdx.x & 31;
    const int g = threadIdx.x >> 5;

    const float* eb = em + (size_t)b * NL * NC;
    float acc = 0.0f;
    #pragma unroll
    for (int l = 0; l < 32; l++) {
        const int ll = g * 32 + l;
        acc += eb[ll * NC + c] * W[ll * NC + c];
    }

    __shared__ float red[8][32];
    red[g][c] = acc;
    __syncthreads();

    if (g == 0) {
        float ssum = 0.0f;
        #pragma unroll
        for (int k = 0; k < 8; k++) ssum += red[k][c];
        out[b * NC + c] = ssum + means[g_state2[b] * NC + c];
    }
}

// =====================================================================
extern "C" void kernel_launch(void* const* d_in, const int* in_sizes, int n_in,
                              void* d_out, int out_size) {
    const float* em    = (const float*)d_in[0];  // emissions (B,L,C)
    const float* tm    = (const float*)d_in[1];  // transition_matrix (S,S)
    const float* idist = (const float*)d_in[2];  // initial_distribution (S,)
    const float* means = (const float*)d_in[3];  // means (S,C)
    const float* cc    = (const float*)d_in[4];  // covar_chol (S,C,C)
    const float* W     = (const float*)d_in[5];  // W (LB,C,PW)
    float* out = (float*)d_out;

    prep_kernel<<<NS + 1, 32>>>(cc, means, tm, idist);

    const size_t shbytes = (size_t)(16896 + 1024) * sizeof(ull) + 128;
    cudaFuncSetAttribute(emlp_kernel, cudaFuncAttributeMaxDynamicSharedMemorySize, (int)shbytes);
    emlp_kernel<<<NROWS / 512, 256, shbytes>>>(em);

    viterbi_kernel<<<NB, 32>>>();

    predict_kernel<<<NB, 256>>>(em, W, means, out);
}